// round 3
// baseline (speedup 1.0000x reference)
#include <cuda_runtime.h>
#include <cstdint>

// ---------------------------------------------------------------------------
// MLPEdgeUpdator via legacy mma.sync tf32 (sm_103 base target: tcgen05 is
// unavailable because the harness compiles compute_103 PTX, not compute_103a).
//
// C[E,256] = concat(edge_feat | node_feat[src_idx] | edge_query)[E,384]
//            @ [W_feat | W_query][384,256] + [b_feat | b_query]
//
// CTA tile: M=128 x N=256, K in 12 chunks of 32. 512 threads = 4x4 warps,
// warp tile 32x64. 3-stage cp.async pipeline. ldmatrix.x4 fragment loads for
// both A and B (swizzled 128B rows). cvt.rna.tf32 for unbiased rounding.
// ---------------------------------------------------------------------------

constexpr int DIMV   = 128;
constexpr int MTILE  = 128;
constexpr int KCH    = 32;
constexpr int NCHUNK = 12;
constexpr int NSTAGE = 3;
constexpr int THREADS = 512;

constexpr int A_BYTES = MTILE * KCH * 4;           // 16384
constexpr int B_BYTES = 256 * KCH * 4;             // 32768
constexpr int STAGE_BYTES = A_BYTES + B_BYTES;     // 49152
constexpr int OFF_IDX   = 0;                       // 128 x int32
constexpr int OFF_BIAS  = 512;                     // 256 x fp32
constexpr int OFF_STAGE = 2048;
constexpr int SMEM_TOTAL = OFF_STAGE + NSTAGE * STAGE_BYTES;  // 149504

__device__ __forceinline__ uint32_t smem_u32(const void* p) {
    uint32_t a;
    asm("{ .reg .u64 t; cvta.to.shared.u64 t, %1; cvt.u32.u64 %0, t; }"
        : "=r"(a) : "l"(p));
    return a;
}

__device__ __forceinline__ void cp_async16(uint32_t dst, const void* src) {
    asm volatile("cp.async.cg.shared.global [%0], [%1], 16;"
                 :: "r"(dst), "l"(src));
}
__device__ __forceinline__ void cp_async4(uint32_t dst, const void* src) {
    asm volatile("cp.async.ca.shared.global [%0], [%1], 4;"
                 :: "r"(dst), "l"(src));
}
#define CP_COMMIT() asm volatile("cp.async.commit_group;")
#define CP_WAIT2()  asm volatile("cp.async.wait_group 2;")

__device__ __forceinline__ void ldsm4(uint32_t* r, uint32_t addr) {
    asm volatile("ldmatrix.sync.aligned.m8n8.x4.shared.b16 {%0,%1,%2,%3}, [%4];"
                 : "=r"(r[0]), "=r"(r[1]), "=r"(r[2]), "=r"(r[3]) : "r"(addr));
}

__device__ __forceinline__ void to_tf32(uint32_t& x) {
    asm volatile("cvt.rna.tf32.f32 %0, %0;" : "+r"(x));
}

__device__ __forceinline__ void mma_tf32(float* d, const uint32_t* a,
                                         uint32_t b0, uint32_t b1) {
    asm volatile(
        "mma.sync.aligned.m16n8k8.row.col.f32.tf32.tf32.f32 "
        "{%0,%1,%2,%3}, {%4,%5,%6,%7}, {%8,%9}, {%0,%1,%2,%3};"
        : "+f"(d[0]), "+f"(d[1]), "+f"(d[2]), "+f"(d[3])
        : "r"(a[0]), "r"(a[1]), "r"(a[2]), "r"(a[3]), "r"(b0), "r"(b1));
}

// int64-vs-int32 src_idx runtime detection (JAX x64 canonicalization ambiguity)
__device__ int g_idx_is64;

__global__ void detect_idx_kernel(const unsigned int* p) {
    if (threadIdx.x == 0) {
        int is64 = 1;
        #pragma unroll
        for (int i = 0; i < 8; i++)
            if (p[2 * i + 1] != 0u) is64 = 0;
        g_idx_is64 = is64;
    }
}

// Fill one pipeline stage with chunk j (A: 128x32 fp32, B: 256x32 fp32).
__device__ __forceinline__ void fill_stage(
    int j, uint32_t stAu, uint32_t stBu, int tid, int row0, int E,
    const int* sidx,
    const float* __restrict__ ef, const float* __restrict__ eq,
    const float* __restrict__ nf,
    const float* __restrict__ Wf, const float* __restrict__ Wq) {
    // ---- A: 1024 x 16B, swizzled 128B rows ----
    #pragma unroll
    for (int i = 0; i < 2; i++) {
        int id = tid + i * THREADS;       // 0..1023
        int r = id >> 3;                  // row 0..127
        int v = id & 7;                   // float4 within row
        int e = row0 + r;
        if (e >= E) e = E - 1;
        const float* src;
        if (j < 4)       src = ef + (size_t)e * DIMV + j * 32;
        else if (j < 8)  src = nf + (size_t)sidx[r] * DIMV + (j - 4) * 32;
        else             src = eq + (size_t)e * DIMV + (j - 8) * 32;
        src += v * 4;
        uint32_t dst = stAu + (uint32_t)(r * 128 + ((v ^ (r & 7)) << 4));
        cp_async16(dst, src);
    }
    // ---- B: transpose W[k][n] -> smem[n][k], 8192 x 4B ----
    // lane decode: kk_low(2) | n_low(3) | n_high(5) | kk_high(3)
    // -> gmem 32B-sector coalesced AND smem 32-bank conflict-free.
    const int kb = j * KCH;
    #pragma unroll
    for (int i = 0; i < 16; i++) {
        int id = tid + i * THREADS;       // 0..8191
        int kk = ((id >> 10) << 2) | (id & 3);         // 0..31
        int n  = ((id >> 5) & 31) * 8 + ((id >> 2) & 7); // 0..255
        const float* src = (n < DIMV)
                               ? (Wf + (size_t)(kb + kk) * DIMV + n)
                               : (Wq + (size_t)(kb + kk) * DIMV + (n - DIMV));
        uint32_t dst = stBu + (uint32_t)(n * 128 + ((kk ^ ((n & 7) << 2)) << 2));
        cp_async4(dst, src);
    }
}

__global__ void __launch_bounds__(THREADS, 1)
mlp_edge_kernel(const float* __restrict__ edge_feat,
                const float* __restrict__ edge_query,
                const float* __restrict__ node_feat,
                const void* __restrict__ src_idx,
                const float* __restrict__ W_feat,
                const float* __restrict__ b_feat,
                const float* __restrict__ W_query,
                const float* __restrict__ b_query,
                float* __restrict__ out, int E) {
    extern __shared__ char smem[];
    const uint32_t sb = smem_u32(smem);
    const int tid = threadIdx.x;
    const int lane = tid & 31;
    const int wid = tid >> 5;
    const int warpM = wid >> 2;   // 0..3
    const int warpN = wid & 3;    // 0..3
    const int row0 = blockIdx.x * MTILE;
    const int is64 = g_idx_is64;

    // gather indices + bias into smem
    if (tid < 128) {
        int e = row0 + tid;
        if (e >= E) e = E - 1;
        int v = is64 ? (int)((const long long*)src_idx)[e]
                     : ((const int*)src_idx)[e];
        ((int*)(smem + OFF_IDX))[tid] = v;
    } else if (tid < 384) {
        int c = tid - 128;
        ((float*)(smem + OFF_BIAS))[c] = (c < DIMV) ? b_feat[c] : b_query[c - DIMV];
    }
    __syncthreads();
    const int* sidx = (const int*)(smem + OFF_IDX);

    // prologue: fill stages 0..2 (chunks 0..2 are all edge_feat)
    #pragma unroll
    for (int j = 0; j < NSTAGE; j++) {
        uint32_t stAu = sb + OFF_STAGE + j * STAGE_BYTES;
        fill_stage(j, stAu, stAu + A_BYTES, tid, row0, E, sidx,
                   edge_feat, edge_query, node_feat, W_feat, W_query);
        CP_COMMIT();
    }

    float acc[2][8][4];
    #pragma unroll
    for (int mt = 0; mt < 2; mt++)
        #pragma unroll
        for (int nt = 0; nt < 8; nt++)
            #pragma unroll
            for (int q = 0; q < 4; q++) acc[mt][nt][q] = 0.f;

    // ldmatrix lane bases
    const int blk = lane >> 3;      // 0..3
    const int rl = lane & 7;        // 0..7
    const int rowA = warpM * 32 + (blk & 1) * 8 + rl;   // + mt*16
    const int cbA = blk >> 1;                            // chunk sub-index
    const int nB = warpN * 64 + (blk >> 1) * 8 + rl;    // + nt2*16
    const int cbB = blk & 1;

    for (int j = 0; j < NCHUNK; j++) {
        const int s = (j < 3) ? j : (j < 6) ? j - 3 : (j < 9) ? j - 6 : j - 9;
        CP_WAIT2();
        __syncthreads();
        const uint32_t stAu = sb + OFF_STAGE + s * STAGE_BYTES;
        const uint32_t stBu = stAu + A_BYTES;

        #pragma unroll
        for (int step = 0; step < 4; step++) {
            uint32_t a[2][4], b[4][4];
            #pragma unroll
            for (int mt = 0; mt < 2; mt++) {
                uint32_t addr = stAu +
                    (uint32_t)((rowA + mt * 16) * 128 +
                               ((((step << 1) + cbA) ^ rl) << 4));
                ldsm4(a[mt], addr);
            }
            #pragma unroll
            for (int nt2 = 0; nt2 < 4; nt2++) {
                uint32_t addr = stBu +
                    (uint32_t)((nB + nt2 * 16) * 128 +
                               ((((step << 1) + cbB) ^ rl) << 4));
                ldsm4(b[nt2], addr);
            }
            #pragma unroll
            for (int mt = 0; mt < 2; mt++)
                #pragma unroll
                for (int q = 0; q < 4; q++) to_tf32(a[mt][q]);
            #pragma unroll
            for (int nt2 = 0; nt2 < 4; nt2++)
                #pragma unroll
                for (int q = 0; q < 4; q++) to_tf32(b[nt2][q]);

            #pragma unroll
            for (int mt = 0; mt < 2; mt++)
                #pragma unroll
                for (int nt = 0; nt < 8; nt++)
                    mma_tf32(acc[mt][nt], a[mt],
                             b[nt >> 1][(nt & 1) * 2],
                             b[nt >> 1][(nt & 1) * 2 + 1]);
        }

        __syncthreads();
        const int jn = j + NSTAGE;
        if (jn < NCHUNK)
            fill_stage(jn, stAu, stBu, tid, row0, E, sidx,
                       edge_feat, edge_query, node_feat, W_feat, W_query);
        CP_COMMIT();
    }

    // ---- epilogue: bias add + store (feat half | query half) ----
    const float* bias = (const float*)(smem + OFF_BIAS);
    const int g = lane >> 2;
    const int tg = lane & 3;
    const int half = warpN >> 1;                  // 0: feat, 1: query
    float* outh = out + (size_t)half * (size_t)E * DIMV;
    const float* biash = bias + half * DIMV;

    #pragma unroll
    for (int mt = 0; mt < 2; mt++) {
        const int rbase = warpM * 32 + mt * 16 + g;
        #pragma unroll
        for (int dr = 0; dr < 2; dr++) {
            const int e = row0 + rbase + dr * 8;
            if (e < E) {
                float* orow = outh + (size_t)e * DIMV;
                #pragma unroll
                for (int nt = 0; nt < 8; nt++) {
                    const int col = (warpN & 1) * 64 + nt * 8 + tg * 2;
                    float2 v;
                    v.x = acc[mt][nt][dr * 2 + 0] + biash[col];
                    v.y = acc[mt][nt][dr * 2 + 1] + biash[col + 1];
                    *(float2*)(orow + col) = v;
                }
            }
        }
    }
}

// ------------------------- launch -------------------------------------------
extern "C" void kernel_launch(void* const* d_in, const int* in_sizes, int n_in,
                              void* d_out, int out_size) {
    const float* edge_feat  = (const float*)d_in[0];
    const float* edge_query = (const float*)d_in[1];
    const float* node_feat  = (const float*)d_in[2];
    const void*  src_idx    = d_in[3];
    const float* W_feat     = (const float*)d_in[4];
    const float* b_feat     = (const float*)d_in[5];
    const float* W_query    = (const float*)d_in[6];
    const float* b_query    = (const float*)d_in[7];
    const int E = in_sizes[0] / DIMV;

    detect_idx_kernel<<<1, 32>>>((const unsigned int*)src_idx);

    static int configured = -1;
    if (configured < 0) {
        cudaFuncSetAttribute(mlp_edge_kernel,
                             cudaFuncAttributeMaxDynamicSharedMemorySize,
                             SMEM_TOTAL);
        configured = 1;
    }
    const int grid = (E + MTILE - 1) / MTILE;
    mlp_edge_kernel<<<grid, THREADS, SMEM_TOTAL>>>(
        edge_feat, edge_query, node_feat, src_idx,
        W_feat, b_feat, W_query, b_query, (float*)d_out, E);
}

// round 4
// speedup vs baseline: 1.4648x; 1.4648x over previous
#include <cuda_runtime.h>
#include <cstdint>

// ---------------------------------------------------------------------------
// MLPEdgeUpdator via legacy mma.sync tf32 (compute_103 target: no tcgen05).
//
// C[E,256] = concat(edge_feat | node_feat[src_idx] | edge_query)[E,384]
//            @ [W_feat | W_query][384,256] + [b_feat | b_query]
//
// R3: B (weights) pre-transposed + swizzled + tf32-pre-rounded ONCE into a
// __device__ global image by a prep kernel; main kernel streams it with
// vectorized 16B cp.async (3x fewer LDGSTS ops, 2/3 of cvt.rna removed).
// CTA tile M=128 x N=256, K = 12 x 32 chunks, 3-stage cp.async pipeline,
// 512 threads = 4x4 warps, warp tile 32x64, ldmatrix.x4 fragment loads.
// ---------------------------------------------------------------------------

constexpr int DIMV   = 128;
constexpr int MTILE  = 128;
constexpr int KCH    = 32;
constexpr int NCHUNK = 12;
constexpr int NSTAGE = 3;
constexpr int THREADS = 512;

constexpr int A_BYTES = MTILE * KCH * 4;           // 16384
constexpr int B_BYTES = 256 * KCH * 4;             // 32768
constexpr int STAGE_BYTES = A_BYTES + B_BYTES;     // 49152
constexpr int OFF_IDX   = 0;                       // 128 x int32
constexpr int OFF_BIAS  = 512;                     // 256 x fp32
constexpr int OFF_STAGE = 2048;
constexpr int SMEM_TOTAL = OFF_STAGE + NSTAGE * STAGE_BYTES;  // 149504

// Pre-swizzled, tf32-pre-rounded B image: 12 chunks x (256 n-rows x 32 k) fp32
__device__ float g_Bimg[NCHUNK * 256 * KCH];
__device__ int g_idx_is64;

__device__ __forceinline__ uint32_t smem_u32(const void* p) {
    uint32_t a;
    asm("{ .reg .u64 t; cvta.to.shared.u64 t, %1; cvt.u32.u64 %0, t; }"
        : "=r"(a) : "l"(p));
    return a;
}

__device__ __forceinline__ void cp_async16(uint32_t dst, const void* src) {
    asm volatile("cp.async.cg.shared.global [%0], [%1], 16;"
                 :: "r"(dst), "l"(src));
}
#define CP_COMMIT() asm volatile("cp.async.commit_group;")
#define CP_WAIT2()  asm volatile("cp.async.wait_group 2;")

__device__ __forceinline__ void ldsm4(uint32_t* r, uint32_t addr) {
    asm volatile("ldmatrix.sync.aligned.m8n8.x4.shared.b16 {%0,%1,%2,%3}, [%4];"
                 : "=r"(r[0]), "=r"(r[1]), "=r"(r[2]), "=r"(r[3]) : "r"(addr));
}

__device__ __forceinline__ void to_tf32(uint32_t& x) {
    asm volatile("cvt.rna.tf32.f32 %0, %0;" : "+r"(x));
}

__device__ __forceinline__ void mma_tf32(float* d, const uint32_t* a,
                                         uint32_t b0, uint32_t b1) {
    asm volatile(
        "mma.sync.aligned.m16n8k8.row.col.f32.tf32.tf32.f32 "
        "{%0,%1,%2,%3}, {%4,%5,%6,%7}, {%8,%9}, {%0,%1,%2,%3};"
        : "+f"(d[0]), "+f"(d[1]), "+f"(d[2]), "+f"(d[3])
        : "r"(a[0]), "r"(a[1]), "r"(a[2]), "r"(a[3]), "r"(b0), "r"(b1));
}

// --------- prep: build swizzled tf32 B image + detect idx width ------------
__global__ void prep_kernel(const float* __restrict__ Wf,
                            const float* __restrict__ Wq,
                            const unsigned int* __restrict__ idx_raw) {
    int t = blockIdx.x * blockDim.x + threadIdx.x;   // 0..98303
    int n = t & 255;
    int kk = (t >> 8) & 31;
    int j = t >> 13;
    float v = (n < DIMV) ? Wf[(size_t)(j * KCH + kk) * DIMV + n]
                         : Wq[(size_t)(j * KCH + kk) * DIMV + (n - DIMV)];
    uint32_t u = __float_as_uint(v);
    to_tf32(u);
    g_Bimg[j * 8192 + n * 32 + (kk ^ ((n & 7) << 2))] = __uint_as_float(u);

    if (t == 0) {
        int is64 = 1;
        #pragma unroll
        for (int i = 0; i < 8; i++)
            if (idx_raw[2 * i + 1] != 0u) is64 = 0;
        g_idx_is64 = is64;
    }
}

// Fill one pipeline stage with chunk j (A: 128x32 fp32, B: 256x32 fp32).
__device__ __forceinline__ void fill_stage(
    int j, uint32_t stAu, uint32_t stBu, int tid, int row0, int E,
    const int* sidx,
    const float* __restrict__ ef, const float* __restrict__ eq,
    const float* __restrict__ nf) {
    // ---- A: 1024 x 16B, swizzled 128B rows ----
    #pragma unroll
    for (int i = 0; i < 2; i++) {
        int id = tid + i * THREADS;       // 0..1023
        int r = id >> 3;                  // row 0..127
        int v = id & 7;                   // float4 within row
        int e = row0 + r;
        if (e >= E) e = E - 1;
        const float* src;
        if (j < 4)       src = ef + (size_t)e * DIMV + j * 32;
        else if (j < 8)  src = nf + (size_t)sidx[r] * DIMV + (j - 4) * 32;
        else             src = eq + (size_t)e * DIMV + (j - 8) * 32;
        src += v * 4;
        uint32_t dst = stAu + (uint32_t)(r * 128 + ((v ^ (r & 7)) << 4));
        cp_async16(dst, src);
    }
    // ---- B: straight 16B copy of pre-swizzled image ----
    const char* bsrc = (const char*)g_Bimg + (size_t)j * B_BYTES;
    #pragma unroll
    for (int i = 0; i < 4; i++) {
        int id = tid + i * THREADS;       // 0..2047
        cp_async16(stBu + (uint32_t)(id * 16), bsrc + (size_t)id * 16);
    }
}

__global__ void __launch_bounds__(THREADS, 1)
mlp_edge_kernel(const float* __restrict__ edge_feat,
                const float* __restrict__ edge_query,
                const float* __restrict__ node_feat,
                const void* __restrict__ src_idx,
                const float* __restrict__ b_feat,
                const float* __restrict__ b_query,
                float* __restrict__ out, int E) {
    extern __shared__ char smem[];
    const uint32_t sb = smem_u32(smem);
    const int tid = threadIdx.x;
    const int lane = tid & 31;
    const int wid = tid >> 5;
    const int warpM = wid >> 2;   // 0..3
    const int warpN = wid & 3;    // 0..3
    const int row0 = blockIdx.x * MTILE;
    const int is64 = g_idx_is64;

    // gather indices + bias into smem
    if (tid < 128) {
        int e = row0 + tid;
        if (e >= E) e = E - 1;
        int v = is64 ? (int)((const long long*)src_idx)[e]
                     : ((const int*)src_idx)[e];
        ((int*)(smem + OFF_IDX))[tid] = v;
    } else if (tid < 384) {
        int c = tid - 128;
        ((float*)(smem + OFF_BIAS))[c] = (c < DIMV) ? b_feat[c] : b_query[c - DIMV];
    }
    __syncthreads();
    const int* sidx = (const int*)(smem + OFF_IDX);

    // prologue: fill stages 0..2
    #pragma unroll
    for (int j = 0; j < NSTAGE; j++) {
        uint32_t stAu = sb + OFF_STAGE + j * STAGE_BYTES;
        fill_stage(j, stAu, stAu + A_BYTES, tid, row0, E, sidx,
                   edge_feat, edge_query, node_feat);
        CP_COMMIT();
    }

    float acc[2][8][4];
    #pragma unroll
    for (int mt = 0; mt < 2; mt++)
        #pragma unroll
        for (int nt = 0; nt < 8; nt++)
            #pragma unroll
            for (int q = 0; q < 4; q++) acc[mt][nt][q] = 0.f;

    // ldmatrix lane bases
    const int blk = lane >> 3;      // 0..3
    const int rl = lane & 7;        // 0..7
    const int rowA = warpM * 32 + (blk & 1) * 8 + rl;   // + mt*16
    const int cbA = blk >> 1;
    const int nB = warpN * 64 + (blk >> 1) * 8 + rl;    // + nt2*16
    const int cbB = blk & 1;

    for (int j = 0; j < NCHUNK; j++) {
        const int s = (j < 3) ? j : (j < 6) ? j - 3 : (j < 9) ? j - 6 : j - 9;
        CP_WAIT2();
        __syncthreads();
        const uint32_t stAu = sb + OFF_STAGE + s * STAGE_BYTES;
        const uint32_t stBu = stAu + A_BYTES;

        #pragma unroll
        for (int step = 0; step < 4; step++) {
            uint32_t a[2][4], b[4][4];
            #pragma unroll
            for (int mt = 0; mt < 2; mt++) {
                uint32_t addr = stAu +
                    (uint32_t)((rowA + mt * 16) * 128 +
                               ((((step << 1) + cbA) ^ rl) << 4));
                ldsm4(a[mt], addr);
            }
            #pragma unroll
            for (int nt2 = 0; nt2 < 4; nt2++) {
                uint32_t addr = stBu +
                    (uint32_t)((nB + nt2 * 16) * 128 +
                               ((((step << 1) + cbB) ^ rl) << 4));
                ldsm4(b[nt2], addr);
            }
            #pragma unroll
            for (int mt = 0; mt < 2; mt++)
                #pragma unroll
                for (int q = 0; q < 4; q++) to_tf32(a[mt][q]);
            // B already tf32-rounded in the prep kernel.

            #pragma unroll
            for (int mt = 0; mt < 2; mt++)
                #pragma unroll
                for (int nt = 0; nt < 8; nt++)
                    mma_tf32(acc[mt][nt], a[mt],
                             b[nt >> 1][(nt & 1) * 2],
                             b[nt >> 1][(nt & 1) * 2 + 1]);
        }

        __syncthreads();
        const int jn = j + NSTAGE;
        if (jn < NCHUNK)
            fill_stage(jn, stAu, stBu, tid, row0, E, sidx,
                       edge_feat, edge_query, node_feat);
        CP_COMMIT();
    }

    // ---- epilogue: bias add + store (feat half | query half) ----
    const float* bias = (const float*)(smem + OFF_BIAS);
    const int g = lane >> 2;
    const int tg = lane & 3;
    const int half = warpN >> 1;                  // 0: feat, 1: query
    float* outh = out + (size_t)half * (size_t)E * DIMV;
    const float* biash = bias + half * DIMV;

    #pragma unroll
    for (int mt = 0; mt < 2; mt++) {
        const int rbase = warpM * 32 + mt * 16 + g;
        #pragma unroll
        for (int dr = 0; dr < 2; dr++) {
            const int e = row0 + rbase + dr * 8;
            if (e < E) {
                float* orow = outh + (size_t)e * DIMV;
                #pragma unroll
                for (int nt = 0; nt < 8; nt++) {
                    const int col = (warpN & 1) * 64 + nt * 8 + tg * 2;
                    float2 v;
                    v.x = acc[mt][nt][dr * 2 + 0] + biash[col];
                    v.y = acc[mt][nt][dr * 2 + 1] + biash[col + 1];
                    *(float2*)(orow + col) = v;
                }
            }
        }
    }
}

// ------------------------- launch -------------------------------------------
extern "C" void kernel_launch(void* const* d_in, const int* in_sizes, int n_in,
                              void* d_out, int out_size) {
    const float* edge_feat  = (const float*)d_in[0];
    const float* edge_query = (const float*)d_in[1];
    const float* node_feat  = (const float*)d_in[2];
    const void*  src_idx    = d_in[3];
    const float* W_feat     = (const float*)d_in[4];
    const float* b_feat     = (const float*)d_in[5];
    const float* W_query    = (const float*)d_in[6];
    const float* b_query    = (const float*)d_in[7];
    const int E = in_sizes[0] / DIMV;

    prep_kernel<<<NCHUNK * 256 * KCH / 256, 256>>>(
        W_feat, W_query, (const unsigned int*)src_idx);

    static int configured = -1;
    if (configured < 0) {
        cudaFuncSetAttribute(mlp_edge_kernel,
                             cudaFuncAttributeMaxDynamicSharedMemorySize,
                             SMEM_TOTAL);
        configured = 1;
    }
    const int grid = (E + MTILE - 1) / MTILE;
    mlp_edge_kernel<<<grid, THREADS, SMEM_TOTAL>>>(
        edge_feat, edge_query, node_feat, src_idx,
        b_feat, b_query, (float*)d_out, E);
}

// round 8
// speedup vs baseline: 1.9106x; 1.3043x over previous
#include <cuda_runtime.h>
#include <cuda_fp16.h>
#include <cstdint>

// ---------------------------------------------------------------------------
// MLPEdgeUpdator via mma.sync.m16n8k16.f16 (compute_103 target: no tcgen05).
//
// C[E,256] = concat(edge_feat | node_feat[src_idx] | edge_query)[E,384]
//            @ [W_feat | W_query][384,256] + [b_feat | b_query]
//
// R4: fp16 inputs (same 11-bit mantissa as tf32) -> tensor ops and LDSM
// traffic both halve. B pre-converted+swizzled to a __device__ fp16 image.
// A cp.async'd fp32 -> smem staging -> converted to swizzled fp16 tile.
// CTA tile M=128 x N=256, K = 12 x 32 chunks, 3-stage pipeline,
// 512 threads = 4x4 warps, warp tile 32x64, ldmatrix.x4 fragments.
// ---------------------------------------------------------------------------

constexpr int DIMV   = 128;
constexpr int MTILE  = 128;
constexpr int KCH    = 32;
constexpr int NCHUNK = 12;
constexpr int NSTAGE = 3;
constexpr int THREADS = 512;

constexpr int A16_BYTES = MTILE * KCH * 2;         // 8192
constexpr int B16_BYTES = 256 * KCH * 2;           // 16384
constexpr int A32_BYTES = MTILE * KCH * 4;         // 16384
constexpr int OFF_A16 = 0;
constexpr int OFF_B16 = A16_BYTES;                 // 8192
constexpr int OFF_A32 = A16_BYTES + B16_BYTES;     // 24576
constexpr int STAGE_BYTES = A16_BYTES + B16_BYTES + A32_BYTES;  // 40960
constexpr int OFF_IDX   = 0;
constexpr int OFF_BIAS  = 512;
constexpr int OFF_STAGE = 2048;
constexpr int SMEM_TOTAL = OFF_STAGE + NSTAGE * STAGE_BYTES;  // 124928

// Pre-swizzled fp16 B image: 12 chunks x 256 n-rows x 32 k
__device__ __half g_Bimg[NCHUNK * 256 * KCH];
__device__ int g_idx_is64;

__device__ __forceinline__ uint32_t smem_u32(const void* p) {
    uint32_t a;
    asm("{ .reg .u64 t; cvta.to.shared.u64 t, %1; cvt.u32.u64 %0, t; }"
        : "=r"(a) : "l"(p));
    return a;
}

__device__ __forceinline__ void cp_async16(uint32_t dst, const void* src) {
    asm volatile("cp.async.cg.shared.global [%0], [%1], 16;"
                 :: "r"(dst), "l"(src));
}
#define CP_COMMIT() asm volatile("cp.async.commit_group;")
#define CP_WAIT2()  asm volatile("cp.async.wait_group 2;")

__device__ __forceinline__ void ldsm4(uint32_t* r, uint32_t addr) {
    asm volatile("ldmatrix.sync.aligned.m8n8.x4.shared.b16 {%0,%1,%2,%3}, [%4];"
                 : "=r"(r[0]), "=r"(r[1]), "=r"(r[2]), "=r"(r[3]) : "r"(addr));
}

__device__ __forceinline__ void mma_f16(float* d, const uint32_t* a,
                                        uint32_t b0, uint32_t b1) {
    asm volatile(
        "mma.sync.aligned.m16n8k16.row.col.f32.f16.f16.f32 "
        "{%0,%1,%2,%3}, {%4,%5,%6,%7}, {%8,%9}, {%0,%1,%2,%3};"
        : "+f"(d[0]), "+f"(d[1]), "+f"(d[2]), "+f"(d[3])
        : "r"(a[0]), "r"(a[1]), "r"(a[2]), "r"(a[3]), "r"(b0), "r"(b1));
}

__device__ __forceinline__ uint32_t pack_h2(float lo, float hi) {
    __half2 h = __floats2half2_rn(lo, hi);
    return *(uint32_t*)&h;
}

// --------- prep: fp16 swizzled B image + idx width detection ---------------
__global__ void prep_kernel(const float* __restrict__ Wf,
                            const float* __restrict__ Wq,
                            const unsigned int* __restrict__ idx_raw) {
    int t = blockIdx.x * blockDim.x + threadIdx.x;   // 0..98303
    int n = t & 255;
    int kk = (t >> 8) & 31;
    int j = t >> 13;
    float v = (n < DIMV) ? Wf[(size_t)(j * KCH + kk) * DIMV + n]
                         : Wq[(size_t)(j * KCH + kk) * DIMV + (n - DIMV)];
    int swc = (kk >> 3) ^ ((n >> 1) & 3);
    g_Bimg[j * 8192 + n * 32 + swc * 8 + (kk & 7)] = __float2half_rn(v);

    if (t == 0) {
        int is64 = 1;
        #pragma unroll
        for (int i = 0; i < 8; i++)
            if (idx_raw[2 * i + 1] != 0u) is64 = 0;
        g_idx_is64 = is64;
    }
}

// Fill one stage with chunk j: A fp32 staging (linear) + B fp16 image copy.
__device__ __forceinline__ void fill_stage(
    int j, uint32_t stg, int tid, int row0, int E, const int* sidx,
    const float* __restrict__ ef, const float* __restrict__ eq,
    const float* __restrict__ nf) {
    // A: 1024 x 16B fp32 into staging, linear (r*128 + v*16)
    #pragma unroll
    for (int i = 0; i < 2; i++) {
        int id = tid + i * THREADS;       // 0..1023
        int r = id >> 3;
        int v = id & 7;
        int e = row0 + r;
        if (e >= E) e = E - 1;
        const float* src;
        if (j < 4)       src = ef + (size_t)e * DIMV + j * 32;
        else if (j < 8)  src = nf + (size_t)sidx[r] * DIMV + (j - 4) * 32;
        else             src = eq + (size_t)e * DIMV + (j - 8) * 32;
        cp_async16(stg + OFF_A32 + (uint32_t)(id * 16), src + v * 4);
    }
    // B: 1024 x 16B straight copy of pre-swizzled fp16 image
    const char* bsrc = (const char*)g_Bimg + (size_t)j * B16_BYTES;
    #pragma unroll
    for (int i = 0; i < 2; i++) {
        int id = tid + i * THREADS;
        cp_async16(stg + OFF_B16 + (uint32_t)(id * 16), bsrc + (size_t)id * 16);
    }
}

__global__ void __launch_bounds__(THREADS, 1)
mlp_edge_kernel(const float* __restrict__ edge_feat,
                const float* __restrict__ edge_query,
                const float* __restrict__ node_feat,
                const void* __restrict__ src_idx,
                const float* __restrict__ b_feat,
                const float* __restrict__ b_query,
                float* __restrict__ out, int E) {
    extern __shared__ char smem[];
    const uint32_t sb = smem_u32(smem);
    const int tid = threadIdx.x;
    const int lane = tid & 31;
    const int wid = tid >> 5;
    const int warpM = wid >> 2;   // 0..3
    const int warpN = wid & 3;    // 0..3
    const int row0 = blockIdx.x * MTILE;
    const int is64 = g_idx_is64;

    if (tid < 128) {
        int e = row0 + tid;
        if (e >= E) e = E - 1;
        int v = is64 ? (int)((const long long*)src_idx)[e]
                     : ((const int*)src_idx)[e];
        ((int*)(smem + OFF_IDX))[tid] = v;
    } else if (tid < 384) {
        int c = tid - 128;
        ((float*)(smem + OFF_BIAS))[c] = (c < DIMV) ? b_feat[c] : b_query[c - DIMV];
    }
    __syncthreads();
    const int* sidx = (const int*)(smem + OFF_IDX);

    #pragma unroll
    for (int j = 0; j < NSTAGE; j++) {
        fill_stage(j, sb + OFF_STAGE + j * STAGE_BYTES, tid, row0, E, sidx,
                   edge_feat, edge_query, node_feat);
        CP_COMMIT();
    }

    float acc[2][8][4];
    #pragma unroll
    for (int mt = 0; mt < 2; mt++)
        #pragma unroll
        for (int nt = 0; nt < 8; nt++)
            #pragma unroll
            for (int q = 0; q < 4; q++) acc[mt][nt][q] = 0.f;

    // ldmatrix lane bases (m16n8k16 quadrant ordering)
    // A tiles: l0-7:(m0-7,klo) l8-15:(m8-15,klo) l16-23:(m0-7,khi) l24-31:(m8-15,khi)
    const int mrow = warpM * 32 + ((lane >> 3) & 1) * 8 + (lane & 7);
    const int cA = lane >> 4;               // 0/1 (klo/khi 16B group)
    const int swA = (mrow >> 1) & 3;        // invariant under +16
    // B tiles: l0-7:(n0-7,klo) l8-15:(n0-7,khi) l16-23:(n8-15,klo) l24-31:(n8-15,khi)
    const int nrow = warpN * 64 + (lane >> 4) * 8 + (lane & 7);
    const int cB = (lane >> 3) & 1;
    const int swB = (nrow >> 1) & 3;

    // convert-pass lane mapping
    const int cvr = tid >> 2;               // row 0..127
    const int cvc = tid & 3;                // 16B fp16 group 0..3
    const uint32_t cv_dst_off =
        (uint32_t)(OFF_A16 + cvr * 64 + ((cvc ^ ((cvr >> 1) & 3)) << 4));
    const uint32_t cv_src_off = (uint32_t)(OFF_A32 + cvr * 128 + cvc * 32);

    for (int j = 0; j < NCHUNK; j++) {
        const int s = (j < 3) ? j : (j < 6) ? j - 3 : (j < 9) ? j - 6 : j - 9;
        const uint32_t stg = sb + OFF_STAGE + s * STAGE_BYTES;
        CP_WAIT2();
        __syncthreads();

        // convert A fp32 staging -> swizzled fp16 tile
        {
            const float4 f0 = *(const float4*)(smem + (stg - sb) + cv_src_off);
            const float4 f1 = *(const float4*)(smem + (stg - sb) + cv_src_off + 16);
            uint4 h;
            h.x = pack_h2(f0.x, f0.y);
            h.y = pack_h2(f0.z, f0.w);
            h.z = pack_h2(f1.x, f1.y);
            h.w = pack_h2(f1.z, f1.w);
            *(uint4*)(smem + (stg - sb) + cv_dst_off) = h;
        }
        __syncthreads();

        #pragma unroll
        for (int step = 0; step < 2; step++) {
            uint32_t a[2][4], b[4][4];
            #pragma unroll
            for (int mt = 0; mt < 2; mt++) {
                uint32_t addr = stg + (uint32_t)(OFF_A16 + (mrow + mt * 16) * 64 +
                                (((step * 2 + cA) ^ swA) << 4));
                ldsm4(a[mt], addr);
            }
            #pragma unroll
            for (int nt2 = 0; nt2 < 4; nt2++) {
                uint32_t addr = stg + (uint32_t)(OFF_B16 + (nrow + nt2 * 16) * 64 +
                                (((step * 2 + cB) ^ swB) << 4));
                ldsm4(b[nt2], addr);
            }
            #pragma unroll
            for (int mt = 0; mt < 2; mt++)
                #pragma unroll
                for (int nt = 0; nt < 8; nt++)
                    mma_f16(acc[mt][nt], a[mt],
                            b[nt >> 1][(nt & 1) * 2],
                            b[nt >> 1][(nt & 1) * 2 + 1]);
        }

        __syncthreads();
        const int jn = j + NSTAGE;
        if (jn < NCHUNK)
            fill_stage(jn, stg, tid, row0, E, sidx,
                       edge_feat, edge_query, node_feat);
        CP_COMMIT();
    }

    // ---- epilogue: bias add + store (feat half | query half) ----
    const float* bias = (const float*)(smem + OFF_BIAS);
    const int g = lane >> 2;
    const int tg = lane & 3;
    const int half = warpN >> 1;
    float* outh = out + (size_t)half * (size_t)E * DIMV;
    const float* biash = bias + half * DIMV;

    #pragma unroll
    for (int mt = 0; mt < 2; mt++) {
        const int rbase = warpM * 32 + mt * 16 + g;
        #pragma unroll
        for (int dr = 0; dr < 2; dr++) {
            const int e = row0 + rbase + dr * 8;
            if (e < E) {
                float* orow = outh + (size_t)e * DIMV;
                #pragma unroll
                for (int nt = 0; nt < 8; nt++) {
                    const int col = (warpN & 1) * 64 + nt * 8 + tg * 2;
                    float2 v;
                    v.x = acc[mt][nt][dr * 2 + 0] + biash[col];
                    v.y = acc[mt][nt][dr * 2 + 1] + biash[col + 1];
                    *(float2*)(orow + col) = v;
                }
            }
        }
    }
}

// ------------------------- launch -------------------------------------------
extern "C" void kernel_launch(void* const* d_in, const int* in_sizes, int n_in,
                              void* d_out, int out_size) {
    const float* edge_feat  = (const float*)d_in[0];
    const float* edge_query = (const float*)d_in[1];
    const float* node_feat  = (const float*)d_in[2];
    const void*  src_idx    = d_in[3];
    const float* W_feat     = (const float*)d_in[4];
    const float* b_feat     = (const float*)d_in[5];
    const float* W_query    = (const float*)d_in[6];
    const float* b_query    = (const float*)d_in[7];
    const int E = in_sizes[0] / DIMV;

    prep_kernel<<<NCHUNK * 256 * KCH / 256, 256>>>(
        W_feat, W_query, (const unsigned int*)src_idx);

    static int configured = -1;
    if (configured < 0) {
        cudaFuncSetAttribute(mlp_edge_kernel,
                             cudaFuncAttributeMaxDynamicSharedMemorySize,
                             SMEM_TOTAL);
        configured = 1;
    }
    const int grid = (E + MTILE - 1) / MTILE;
    mlp_edge_kernel<<<grid, THREADS, SMEM_TOTAL>>>(
        edge_feat, edge_query, node_feat, src_idx,
        b_feat, b_query, (float*)d_out, E);
}

// round 10
// speedup vs baseline: 2.0508x; 1.0734x over previous
#include <cuda_runtime.h>
#include <cuda_fp16.h>
#include <cstdint>

// ---------------------------------------------------------------------------
// MLPEdgeUpdator via mma.sync.m16n8k16.f16 (compute_103 target: no tcgen05).
//
// C[E,256] = concat(edge_feat | node_feat[src_idx] | edge_query)[E,384]
//            @ [W_feat | W_query][384,256] + [b_feat | b_query]
//
// R5: (1) A loads go LDG -> register fp16 convert -> direct swizzled STS
//     (removes 32 KB/chunk of smem staging traffic);
//     (2) 8 warps, warp tile 64x64 (halves LDSM fragment redundancy).
// CTA tile M=128 x N=256, K = 12 x 32 chunks, B 3-stage cp.async from a
// pre-swizzled fp16 weight image, A single-buffer fp16 tile (sync-protected).
// ---------------------------------------------------------------------------

constexpr int DIMV   = 128;
constexpr int MTILE  = 128;
constexpr int KCH    = 32;
constexpr int NCHUNK = 12;
constexpr int NSTAGE = 3;
constexpr int THREADS = 256;

constexpr int A16_BYTES = MTILE * KCH * 2;         // 8192
constexpr int B16_BYTES = 256 * KCH * 2;           // 16384
constexpr int OFF_IDX  = 0;                        // 128 x int32
constexpr int OFF_BIAS = 512;                      // 256 x fp32
constexpr int OFF_A16  = 2048;
constexpr int OFF_B    = OFF_A16 + A16_BYTES;      // 10240
constexpr int SMEM_TOTAL = OFF_B + NSTAGE * B16_BYTES;  // 59392

// Pre-swizzled fp16 B image: 12 chunks x 256 n-rows x 32 k
__device__ __half g_Bimg[NCHUNK * 256 * KCH];
__device__ int g_idx_is64;

__device__ __forceinline__ uint32_t smem_u32(const void* p) {
    uint32_t a;
    asm("{ .reg .u64 t; cvta.to.shared.u64 t, %1; cvt.u32.u64 %0, t; }"
        : "=r"(a) : "l"(p));
    return a;
}

__device__ __forceinline__ void cp_async16(uint32_t dst, const void* src) {
    asm volatile("cp.async.cg.shared.global [%0], [%1], 16;"
                 :: "r"(dst), "l"(src));
}
#define CP_COMMIT() asm volatile("cp.async.commit_group;")
#define CP_WAIT2()  asm volatile("cp.async.wait_group 2;")

__device__ __forceinline__ void ldsm4(uint32_t* r, uint32_t addr) {
    asm volatile("ldmatrix.sync.aligned.m8n8.x4.shared.b16 {%0,%1,%2,%3}, [%4];"
                 : "=r"(r[0]), "=r"(r[1]), "=r"(r[2]), "=r"(r[3]) : "r"(addr));
}

__device__ __forceinline__ void mma_f16(float* d, const uint32_t* a,
                                        uint32_t b0, uint32_t b1) {
    asm volatile(
        "mma.sync.aligned.m16n8k16.row.col.f32.f16.f16.f32 "
        "{%0,%1,%2,%3}, {%4,%5,%6,%7}, {%8,%9}, {%0,%1,%2,%3};"
        : "+f"(d[0]), "+f"(d[1]), "+f"(d[2]), "+f"(d[3])
        : "r"(a[0]), "r"(a[1]), "r"(a[2]), "r"(a[3]), "r"(b0), "r"(b1));
}

__device__ __forceinline__ uint32_t pack_h2(float lo, float hi) {
    __half2 h = __floats2half2_rn(lo, hi);
    return *(uint32_t*)&h;
}

// --------- prep: fp16 swizzled B image + idx width detection ---------------
__global__ void prep_kernel(const float* __restrict__ Wf,
                            const float* __restrict__ Wq,
                            const unsigned int* __restrict__ idx_raw) {
    int t = blockIdx.x * blockDim.x + threadIdx.x;   // 0..98303
    int n = t & 255;
    int kk = (t >> 8) & 31;
    int j = t >> 13;
    float v = (n < DIMV) ? Wf[(size_t)(j * KCH + kk) * DIMV + n]
                         : Wq[(size_t)(j * KCH + kk) * DIMV + (n - DIMV)];
    int swc = (kk >> 3) ^ ((n >> 1) & 3);
    g_Bimg[j * 8192 + n * 32 + swc * 8 + (kk & 7)] = __float2half_rn(v);

    if (t == 0) {
        int is64 = 1;
        #pragma unroll
        for (int i = 0; i < 8; i++)
            if (idx_raw[2 * i + 1] != 0u) is64 = 0;
        g_idx_is64 = is64;
    }
}

// A: each thread owns 64B fp32 of the chunk (quarter-row x2): LDG to regs.
__device__ __forceinline__ void load_A(
    int j, int tid, int row0, int E, const int* sidx,
    const float* __restrict__ ef, const float* __restrict__ eq,
    const float* __restrict__ nf, float4* fA) {
    #pragma unroll
    for (int i = 0; i < 2; i++) {
        int id = tid + i * THREADS;     // 0..511
        int r = id >> 2;                // row 0..127
        int q = id & 3;                 // 32B group within row
        int e = row0 + r;
        if (e >= E) e = E - 1;
        const float* src;
        if (j < 4)       src = ef + (size_t)e * DIMV + j * 32;
        else if (j < 8)  src = nf + (size_t)sidx[r] * DIMV + (j - 4) * 32;
        else             src = eq + (size_t)e * DIMV + (j - 8) * 32;
        src += q * 8;
        fA[i * 2]     = *(const float4*)src;
        fA[i * 2 + 1] = *(const float4*)(src + 4);
    }
}

// B: straight 16B copy of pre-swizzled fp16 image (L2-hot).
__device__ __forceinline__ void fill_B(int j, uint32_t stB, int tid) {
    const char* bsrc = (const char*)g_Bimg + (size_t)j * B16_BYTES;
    #pragma unroll
    for (int i = 0; i < 4; i++) {
        int id = tid + i * THREADS;     // 0..1023
        cp_async16(stB + (uint32_t)(id * 16), bsrc + (size_t)id * 16);
    }
}

__global__ void __launch_bounds__(THREADS, 1)
mlp_edge_kernel(const float* __restrict__ edge_feat,
                const float* __restrict__ edge_query,
                const float* __restrict__ node_feat,
                const void* __restrict__ src_idx,
                const float* __restrict__ b_feat,
                const float* __restrict__ b_query,
                float* __restrict__ out, int E) {
    extern __shared__ char smem[];
    const uint32_t sb = smem_u32(smem);
    const int tid = threadIdx.x;
    const int lane = tid & 31;
    const int wid = tid >> 5;
    const int warpM = wid >> 2;   // 0..1 (64-row slabs)
    const int warpN = wid & 3;    // 0..3 (64-col slabs)
    const int row0 = blockIdx.x * MTILE;
    const int is64 = g_idx_is64;

    if (tid < 128) {
        int e = row0 + tid;
        if (e >= E) e = E - 1;
        int v = is64 ? (int)((const long long*)src_idx)[e]
                     : ((const int*)src_idx)[e];
        ((int*)(smem + OFF_IDX))[tid] = v;
    }
    ((float*)(smem + OFF_BIAS))[tid] =
        (tid < DIMV) ? b_feat[tid] : b_query[tid - DIMV];
    __syncthreads();
    const int* sidx = (const int*)(smem + OFF_IDX);

    // prologue: A chunk 0 into regs; B stages 0..2 in flight
    float4 fA[4];
    load_A(0, tid, row0, E, sidx, edge_feat, edge_query, node_feat, fA);
    #pragma unroll
    for (int j = 0; j < NSTAGE; j++) {
        fill_B(j, sb + OFF_B + j * B16_BYTES, tid);
        CP_COMMIT();
    }

    float acc[4][8][4];
    #pragma unroll
    for (int mt = 0; mt < 4; mt++)
        #pragma unroll
        for (int nt = 0; nt < 8; nt++)
            #pragma unroll
            for (int q = 0; q < 4; q++) acc[mt][nt][q] = 0.f;

    // ldmatrix lane bases (m16n8k16 quadrant ordering)
    const int mrow = warpM * 64 + ((lane >> 3) & 1) * 8 + (lane & 7);
    const int cA = lane >> 4;
    const int swA = (mrow >> 1) & 3;        // invariant under +16
    const int nrow = warpN * 64 + (lane >> 4) * 8 + (lane & 7);
    const int cB = (lane >> 3) & 1;
    const int swB = (nrow >> 1) & 3;

    // A STS addressing (per-thread, fixed across chunks)
    const int ar = (tid >> 2);              // wrong for id>=256; compute inline
    (void)ar;

    for (int j = 0; j < NCHUNK; j++) {
        const int s = (j < 3) ? j : (j < 6) ? j - 3 : (j < 9) ? j - 6 : j - 9;
        const uint32_t stB = sb + OFF_B + s * B16_BYTES;
        CP_WAIT2();
        __syncthreads();

        // registers (chunk j) -> swizzled fp16 A tile
        #pragma unroll
        for (int i = 0; i < 2; i++) {
            int id = tid + i * THREADS;
            int r = id >> 2;
            int q = id & 3;
            uint4 h;
            h.x = pack_h2(fA[i * 2].x,     fA[i * 2].y);
            h.y = pack_h2(fA[i * 2].z,     fA[i * 2].w);
            h.z = pack_h2(fA[i * 2 + 1].x, fA[i * 2 + 1].y);
            h.w = pack_h2(fA[i * 2 + 1].z, fA[i * 2 + 1].w);
            *(uint4*)(smem + OFF_A16 + r * 64 + ((q ^ ((r >> 1) & 3)) << 4)) = h;
        }
        __syncthreads();

        // prefetch A for next chunk (covered by the MMA below)
        if (j + 1 < NCHUNK)
            load_A(j + 1, tid, row0, E, sidx,
                   edge_feat, edge_query, node_feat, fA);

        #pragma unroll
        for (int step = 0; step < 2; step++) {
            uint32_t a[4][4], b[4][4];
            #pragma unroll
            for (int mt = 0; mt < 4; mt++) {
                uint32_t addr = sb + (uint32_t)(OFF_A16 + (mrow + mt * 16) * 64 +
                                (((step * 2 + cA) ^ swA) << 4));
                ldsm4(a[mt], addr);
            }
            #pragma unroll
            for (int nt2 = 0; nt2 < 4; nt2++) {
                uint32_t addr = stB + (uint32_t)((nrow + nt2 * 16) * 64 +
                                (((step * 2 + cB) ^ swB) << 4));
                ldsm4(b[nt2], addr);
            }
            #pragma unroll
            for (int mt = 0; mt < 4; mt++)
                #pragma unroll
                for (int nt = 0; nt < 8; nt++)
                    mma_f16(acc[mt][nt], a[mt],
                            b[nt >> 1][(nt & 1) * 2],
                            b[nt >> 1][(nt & 1) * 2 + 1]);
        }

        __syncthreads();
        const int jn = j + NSTAGE;
        if (jn < NCHUNK)
            fill_B(jn, stB, tid);
        CP_COMMIT();   // unconditional: keeps wait_group arithmetic aligned
    }

    // ---- epilogue: bias add + store (feat half | query half) ----
    const float* bias = (const float*)(smem + OFF_BIAS);
    const int g = lane >> 2;
    const int tg = lane & 3;
    const int half = warpN >> 1;
    float* outh = out + (size_t)half * (size_t)E * DIMV;
    const float* biash = bias + half * DIMV;

    #pragma unroll
    for (int mt = 0; mt < 4; mt++) {
        const int rbase = warpM * 64 + mt * 16 + g;
        #pragma unroll
        for (int dr = 0; dr < 2; dr++) {
            const int e = row0 + rbase + dr * 8;
            if (e < E) {
                float* orow = outh + (size_t)e * DIMV;
                #pragma unroll
                for (int nt = 0; nt < 8; nt++) {
                    const int col = (warpN & 1) * 64 + nt * 8 + tg * 2;
                    float2 v;
                    v.x = acc[mt][nt][dr * 2 + 0] + biash[col];
                    v.y = acc[mt][nt][dr * 2 + 1] + biash[col + 1];
                    *(float2*)(orow + col) = v;
                }
            }
        }
    }
}

// ------------------------- launch -------------------------------------------
extern "C" void kernel_launch(void* const* d_in, const int* in_sizes, int n_in,
                              void* d_out, int out_size) {
    const float* edge_feat  = (const float*)d_in[0];
    const float* edge_query = (const float*)d_in[1];
    const float* node_feat  = (const float*)d_in[2];
    const void*  src_idx    = d_in[3];
    const float* W_feat     = (const float*)d_in[4];
    const float* b_feat     = (const float*)d_in[5];
    const float* W_query    = (const float*)d_in[6];
    const float* b_query    = (const float*)d_in[7];
    const int E = in_sizes[0] / DIMV;

    prep_kernel<<<NCHUNK * 256 * KCH / 256, 256>>>(
        W_feat, W_query, (const unsigned int*)src_idx);

    static int configured = -1;
    if (configured < 0) {
        cudaFuncSetAttribute(mlp_edge_kernel,
                             cudaFuncAttributeMaxDynamicSharedMemorySize,
                             SMEM_TOTAL);
        configured = 1;
    }
    const int grid = (E + MTILE - 1) / MTILE;
    mlp_edge_kernel<<<grid, THREADS, SMEM_TOTAL>>>(
        edge_feat, edge_query, node_feat, src_idx,
        b_feat, b_query, (float*)d_out, E);
}

// round 11
// speedup vs baseline: 2.1008x; 1.0244x over previous
#include <cuda_runtime.h>
#include <cuda_fp16.h>
#include <cstdint>

// ---------------------------------------------------------------------------
// MLPEdgeUpdator via mma.sync.m16n8k16.f16 (compute_103 target: no tcgen05).
//
// C[E,256] = concat(edge_feat | node_feat[src_idx] | edge_query)[E,384]
//            @ [W_feat | W_query][384,256] + [b_feat | b_query]
//
// R6: ONE __syncthreads per K-chunk (was 3). A16 tile double-buffered;
// B uses 4 smem stages with prefetch distance 3 so cp.async fills, A LDG
// prefetch, and HMMAs all overlap within a chunk.
// CTA tile M=128 x N=256, 8 warps (64x64 warp tile), K = 12 x 32 chunks.
// B streams from a pre-swizzled fp16 weight image (prep kernel, L2-hot).
// ---------------------------------------------------------------------------

constexpr int DIMV   = 128;
constexpr int MTILE  = 128;
constexpr int KCH    = 32;
constexpr int NCHUNK = 12;
constexpr int THREADS = 256;

constexpr int A16_BYTES = MTILE * KCH * 2;         // 8192 (per buffer)
constexpr int B16_BYTES = 256 * KCH * 2;           // 16384 (per stage)
constexpr int OFF_IDX  = 0;                        // 128 x int32
constexpr int OFF_BIAS = 512;                      // 256 x fp32
constexpr int OFF_A16  = 2048;                     // 2 buffers
constexpr int OFF_B    = OFF_A16 + 2 * A16_BYTES;  // 18432, 4 stages
constexpr int SMEM_TOTAL = OFF_B + 4 * B16_BYTES;  // 83968

// Pre-swizzled fp16 B image: 12 chunks x 256 n-rows x 32 k
__device__ __half g_Bimg[NCHUNK * 256 * KCH];
__device__ int g_idx_is64;

__device__ __forceinline__ uint32_t smem_u32(const void* p) {
    uint32_t a;
    asm("{ .reg .u64 t; cvta.to.shared.u64 t, %1; cvt.u32.u64 %0, t; }"
        : "=r"(a) : "l"(p));
    return a;
}

__device__ __forceinline__ void cp_async16(uint32_t dst, const void* src) {
    asm volatile("cp.async.cg.shared.global [%0], [%1], 16;"
                 :: "r"(dst), "l"(src));
}
#define CP_COMMIT() asm volatile("cp.async.commit_group;")
#define CP_WAIT2()  asm volatile("cp.async.wait_group 2;")

__device__ __forceinline__ void ldsm4(uint32_t* r, uint32_t addr) {
    asm volatile("ldmatrix.sync.aligned.m8n8.x4.shared.b16 {%0,%1,%2,%3}, [%4];"
                 : "=r"(r[0]), "=r"(r[1]), "=r"(r[2]), "=r"(r[3]) : "r"(addr));
}

__device__ __forceinline__ void mma_f16(float* d, const uint32_t* a,
                                        uint32_t b0, uint32_t b1) {
    asm volatile(
        "mma.sync.aligned.m16n8k16.row.col.f32.f16.f16.f32 "
        "{%0,%1,%2,%3}, {%4,%5,%6,%7}, {%8,%9}, {%0,%1,%2,%3};"
        : "+f"(d[0]), "+f"(d[1]), "+f"(d[2]), "+f"(d[3])
        : "r"(a[0]), "r"(a[1]), "r"(a[2]), "r"(a[3]), "r"(b0), "r"(b1));
}

__device__ __forceinline__ uint32_t pack_h2(float lo, float hi) {
    __half2 h = __floats2half2_rn(lo, hi);
    return *(uint32_t*)&h;
}

// --------- prep: fp16 swizzled B image + idx width detection ---------------
__global__ void prep_kernel(const float* __restrict__ Wf,
                            const float* __restrict__ Wq,
                            const unsigned int* __restrict__ idx_raw) {
    int t = blockIdx.x * blockDim.x + threadIdx.x;   // 0..98303
    int n = t & 255;
    int kk = (t >> 8) & 31;
    int j = t >> 13;
    float v = (n < DIMV) ? Wf[(size_t)(j * KCH + kk) * DIMV + n]
                         : Wq[(size_t)(j * KCH + kk) * DIMV + (n - DIMV)];
    int swc = (kk >> 3) ^ ((n >> 1) & 3);
    g_Bimg[j * 8192 + n * 32 + swc * 8 + (kk & 7)] = __float2half_rn(v);

    if (t == 0) {
        int is64 = 1;
        #pragma unroll
        for (int i = 0; i < 8; i++)
            if (idx_raw[2 * i + 1] != 0u) is64 = 0;
        g_idx_is64 = is64;
    }
}

// A: each thread owns 64B fp32 of the chunk (two half-rows): LDG to regs.
__device__ __forceinline__ void load_A(
    int j, int tid, int row0, int E, const int* sidx,
    const float* __restrict__ ef, const float* __restrict__ eq,
    const float* __restrict__ nf, float4* fA) {
    #pragma unroll
    for (int i = 0; i < 2; i++) {
        int id = tid + i * THREADS;     // 0..511
        int r = id >> 2;                // row 0..127
        int q = id & 3;                 // 32B group within row
        int e = row0 + r;
        if (e >= E) e = E - 1;
        const float* src;
        if (j < 4)       src = ef + (size_t)e * DIMV + j * 32;
        else if (j < 8)  src = nf + (size_t)sidx[r] * DIMV + (j - 4) * 32;
        else             src = eq + (size_t)e * DIMV + (j - 8) * 32;
        src += q * 8;
        fA[i * 2]     = *(const float4*)src;
        fA[i * 2 + 1] = *(const float4*)(src + 4);
    }
}

// B: straight 16B copy of pre-swizzled fp16 image (L2-hot).
__device__ __forceinline__ void fill_B(int j, uint32_t stB, int tid) {
    const char* bsrc = (const char*)g_Bimg + (size_t)j * B16_BYTES;
    #pragma unroll
    for (int i = 0; i < 4; i++) {
        int id = tid + i * THREADS;     // 0..1023
        cp_async16(stB + (uint32_t)(id * 16), bsrc + (size_t)id * 16);
    }
}

__global__ void __launch_bounds__(THREADS, 1)
mlp_edge_kernel(const float* __restrict__ edge_feat,
                const float* __restrict__ edge_query,
                const float* __restrict__ node_feat,
                const void* __restrict__ src_idx,
                const float* __restrict__ b_feat,
                const float* __restrict__ b_query,
                float* __restrict__ out, int E) {
    extern __shared__ char smem[];
    const uint32_t sb = smem_u32(smem);
    const int tid = threadIdx.x;
    const int lane = tid & 31;
    const int wid = tid >> 5;
    const int warpM = wid >> 2;   // 0..1 (64-row slabs)
    const int warpN = wid & 3;    // 0..3 (64-col slabs)
    const int row0 = blockIdx.x * MTILE;
    const int is64 = g_idx_is64;

    if (tid < 128) {
        int e = row0 + tid;
        if (e >= E) e = E - 1;
        int v = is64 ? (int)((const long long*)src_idx)[e]
                     : ((const int*)src_idx)[e];
        ((int*)(smem + OFF_IDX))[tid] = v;
    }
    ((float*)(smem + OFF_BIAS))[tid] =
        (tid < DIMV) ? b_feat[tid] : b_query[tid - DIMV];
    __syncthreads();
    const int* sidx = (const int*)(smem + OFF_IDX);

    // prologue: A chunk 0 into regs; B chunks 0..2 in flight (stages 0..2)
    float4 fA[4];
    load_A(0, tid, row0, E, sidx, edge_feat, edge_query, node_feat, fA);
    #pragma unroll
    for (int j = 0; j < 3; j++) {
        fill_B(j, sb + OFF_B + j * B16_BYTES, tid);
        CP_COMMIT();
    }

    float acc[4][8][4];
    #pragma unroll
    for (int mt = 0; mt < 4; mt++)
        #pragma unroll
        for (int nt = 0; nt < 8; nt++)
            #pragma unroll
            for (int q = 0; q < 4; q++) acc[mt][nt][q] = 0.f;

    // ldmatrix lane bases (m16n8k16 quadrant ordering)
    const int mrow = warpM * 64 + ((lane >> 3) & 1) * 8 + (lane & 7);
    const int cA = lane >> 4;
    const int swA = (mrow >> 1) & 3;        // invariant under +16
    const int nrow = warpN * 64 + (lane >> 4) * 8 + (lane & 7);
    const int cB = (lane >> 3) & 1;
    const int swB = (nrow >> 1) & 3;

    // A STS per-thread addresses (fixed across chunks, modulo buffer select)
    const int r0a = tid >> 2, q0a = tid & 3;
    const int r1a = (tid + THREADS) >> 2, q1a = tid & 3;
    const uint32_t stsA0 =
        (uint32_t)(OFF_A16 + r0a * 64 + ((q0a ^ ((r0a >> 1) & 3)) << 4));
    const uint32_t stsA1 =
        (uint32_t)(OFF_A16 + r1a * 64 + ((q1a ^ ((r1a >> 1) & 3)) << 4));

    for (int j = 0; j < NCHUNK; j++) {
        const uint32_t stB = sb + OFF_B + (j & 3) * B16_BYTES;
        const uint32_t abuf = (uint32_t)((j & 1) * A16_BYTES);
        CP_WAIT2();                       // B chunk j landed

        // regs (chunk j) -> swizzled fp16 A tile, buffer j&1
        {
            uint4 h0, h1;
            h0.x = pack_h2(fA[0].x, fA[0].y);
            h0.y = pack_h2(fA[0].z, fA[0].w);
            h0.z = pack_h2(fA[1].x, fA[1].y);
            h0.w = pack_h2(fA[1].z, fA[1].w);
            h1.x = pack_h2(fA[2].x, fA[2].y);
            h1.y = pack_h2(fA[2].z, fA[2].w);
            h1.z = pack_h2(fA[3].x, fA[3].y);
            h1.w = pack_h2(fA[3].z, fA[3].w);
            *(uint4*)(smem + stsA0 + abuf) = h0;
            *(uint4*)(smem + stsA1 + abuf) = h1;
        }
        __syncthreads();                  // the ONLY barrier in the chunk

        // overlap work: A LDGs for j+1, B cp.async for j+3 (targets stage
        // (j+3)&3 == (j-1)&3, whose readers all passed the barrier above)
        if (j + 1 < NCHUNK)
            load_A(j + 1, tid, row0, E, sidx,
                   edge_feat, edge_query, node_feat, fA);
        if (j + 3 < NCHUNK)
            fill_B(j + 3, sb + OFF_B + ((j + 3) & 3) * B16_BYTES, tid);
        CP_COMMIT();                      // unconditional: wait arithmetic

        #pragma unroll
        for (int step = 0; step < 2; step++) {
            uint32_t a[4][4], b[4][4];
            #pragma unroll
            for (int mt = 0; mt < 4; mt++) {
                uint32_t addr = sb + abuf +
                    (uint32_t)(OFF_A16 + (mrow + mt * 16) * 64 +
                               (((step * 2 + cA) ^ swA) << 4));
                ldsm4(a[mt], addr);
            }
            #pragma unroll
            for (int nt2 = 0; nt2 < 4; nt2++) {
                uint32_t addr = stB + (uint32_t)((nrow + nt2 * 16) * 64 +
                                (((step * 2 + cB) ^ swB) << 4));
                ldsm4(b[nt2], addr);
            }
            #pragma unroll
            for (int mt = 0; mt < 4; mt++)
                #pragma unroll
                for (int nt = 0; nt < 8; nt++)
                    mma_f16(acc[mt][nt], a[mt],
                            b[nt >> 1][(nt & 1) * 2],
                            b[nt >> 1][(nt & 1) * 2 + 1]);
        }
        // no trailing barrier: next iteration's STS targets the other A
        // buffer, and its sync orders everything else.
    }

    // ---- epilogue: bias add + store (feat half | query half) ----
    const float* bias = (const float*)(smem + OFF_BIAS);
    const int g = lane >> 2;
    const int tg = lane & 3;
    const int half = warpN >> 1;
    float* outh = out + (size_t)half * (size_t)E * DIMV;
    const float* biash = bias + half * DIMV;

    #pragma unroll
    for (int mt = 0; mt < 4; mt++) {
        const int rbase = warpM * 64 + mt * 16 + g;
        #pragma unroll
        for (int dr = 0; dr < 2; dr++) {
            const int e = row0 + rbase + dr * 8;
            if (e < E) {
                float* orow = outh + (size_t)e * DIMV;
                #pragma unroll
                for (int nt = 0; nt < 8; nt++) {
                    const int col = (warpN & 1) * 64 + nt * 8 + tg * 2;
                    float2 v;
                    v.x = acc[mt][nt][dr * 2 + 0] + biash[col];
                    v.y = acc[mt][nt][dr * 2 + 1] + biash[col + 1];
                    *(float2*)(orow + col) = v;
                }
            }
        }
    }
}

// ------------------------- launch -------------------------------------------
extern "C" void kernel_launch(void* const* d_in, const int* in_sizes, int n_in,
                              void* d_out, int out_size) {
    const float* edge_feat  = (const float*)d_in[0];
    const float* edge_query = (const float*)d_in[1];
    const float* node_feat  = (const float*)d_in[2];
    const void*  src_idx    = d_in[3];
    const float* W_feat     = (const float*)d_in[4];
    const float* b_feat     = (const float*)d_in[5];
    const float* W_query    = (const float*)d_in[6];
    const float* b_query    = (const float*)d_in[7];
    const int E = in_sizes[0] / DIMV;

    prep_kernel<<<NCHUNK * 256 * KCH / 256, 256>>>(
        W_feat, W_query, (const unsigned int*)src_idx);

    static int configured = -1;
    if (configured < 0) {
        cudaFuncSetAttribute(mlp_edge_kernel,
                             cudaFuncAttributeMaxDynamicSharedMemorySize,
                             SMEM_TOTAL);
        configured = 1;
    }
    const int grid = (E + MTILE - 1) / MTILE;
    mlp_edge_kernel<<<grid, THREADS, SMEM_TOTAL>>>(
        edge_feat, edge_query, node_feat, src_idx,
        b_feat, b_query, (float*)d_out, E);
}